// round 1
// baseline (speedup 1.0000x reference)
#include <cuda_runtime.h>
#include <math.h>

#define NN 50000
#define NE 800000
#define EPSV 1e-5f

// ---------------- scratch (static __device__, no allocation) ----------------
__device__ __align__(16) float g_h1[51200000];     // [E,64] pre-BN edge hidden
__device__ __align__(16) float g_xw1[NN * 64];     // x @ w1m_top + b1m
__device__ __align__(16) float g_Sa[NN * 64];      // scatter-sum of relu(bn(h1))
__device__ __align__(16) float g_cnt[NN];
__device__ __align__(16) float g_h1n[NN * 64];     // pre-BN node hidden
__device__ __align__(16) float g_wcomb[128 * 64];  // [w1n_top ; w2m@w1n_bot]
__device__ __align__(16) float g_bc[64];           // b2m @ w1n_bot
__device__ __align__(16) float g_estats[128];      // sum | sumsq (edge BN)
__device__ __align__(16) float g_nstats[128];      // sum | sumsq (node BN)
__device__ __align__(16) float g_escale[64];
__device__ __align__(16) float g_eshift[64];
__device__ __align__(16) float g_nscale[64];
__device__ __align__(16) float g_nshift[64];

#define MMA_ROW(ar, a) do { \
  ar[0]=fmaf(a.x,b0.x,ar[0]); ar[0]=fmaf(a.y,b1.x,ar[0]); ar[0]=fmaf(a.z,b2.x,ar[0]); ar[0]=fmaf(a.w,b3.x,ar[0]); \
  ar[1]=fmaf(a.x,b0.y,ar[1]); ar[1]=fmaf(a.y,b1.y,ar[1]); ar[1]=fmaf(a.z,b2.y,ar[1]); ar[1]=fmaf(a.w,b3.y,ar[1]); \
  ar[2]=fmaf(a.x,b0.z,ar[2]); ar[2]=fmaf(a.y,b1.z,ar[2]); ar[2]=fmaf(a.z,b2.z,ar[2]); ar[2]=fmaf(a.w,b3.z,ar[2]); \
  ar[3]=fmaf(a.x,b0.w,ar[3]); ar[3]=fmaf(a.y,b1.w,ar[3]); ar[3]=fmaf(a.z,b2.w,ar[3]); ar[3]=fmaf(a.w,b3.w,ar[3]); \
} while(0)

// ---------------- zero accumulators ----------------
__global__ void k_zero() {
  size_t i = (size_t)blockIdx.x * 256 + threadIdx.x;
  const size_t nsa = (size_t)NN * 64;
  if (i < nsa) { g_Sa[i] = 0.f; return; }
  i -= nsa;
  if (i < NN) { g_cnt[i] = 0.f; return; }
  i -= NN;
  if (i < 128) { g_estats[i] = 0.f; return; }
  i -= 128;
  if (i < 128) { g_nstats[i] = 0.f; return; }
}

// ---------------- fold w2m into w1n_bot: wcomb = [w1n_top ; w2m@w1n_bot] ----
__global__ void k_wprep(const float* __restrict__ w1n, const float* __restrict__ w2m,
                        const float* __restrict__ b2m) {
  int b = blockIdx.x, t = threadIdx.x;     // 16 blocks x 256 threads
  g_wcomb[b * 256 + t] = w1n[b * 256 + t]; // copy top 64 rows (4096 entries)
  int k = b * 4 + (t >> 6), j = t & 63;    // Wc[k][j]
  float s = 0.f;
  for (int q = 0; q < 64; q++) s = fmaf(w2m[k * 64 + q], w1n[(64 + q) * 64 + j], s);
  g_wcomb[(64 + k) * 64 + j] = s;
  if (b == 0 && t < 64) {
    float sb = 0.f;
    for (int q = 0; q < 64; q++) sb = fmaf(b2m[q], w1n[(64 + q) * 64 + t], sb);
    g_bc[t] = sb;
  }
}

// ---------------- xw1 = x @ w1m[0:64] + b1m ----------------
__global__ __launch_bounds__(256) void k_xw1(const float* __restrict__ x,
                                             const float* __restrict__ w1m,
                                             const float* __restrict__ b1m) {
  __shared__ float As[64 * 64];
  __shared__ float Ws[64 * 64];
  int n0 = blockIdx.x * 64;
  int tid = threadIdx.x;
  for (int i = tid; i < 64 * 16; i += 256) {
    int r = i >> 4, q = i & 15;
    *(float4*)&Ws[r * 64 + q * 4] = ((const float4*)w1m)[r * 16 + q];
  }
  for (int i = tid; i < 64 * 16; i += 256) {
    int r = i >> 4, q = i & 15;
    float4 v = make_float4(0.f, 0.f, 0.f, 0.f);
    if (n0 + r < NN) v = ((const float4*)x)[(size_t)(n0 + r) * 16 + q];
    *(float4*)&As[r * 64 + q * 4] = v;
  }
  __syncthreads();
  int tx = tid & 15, ty = tid >> 4;
  float acc[4][4] = {};
#pragma unroll 4
  for (int kq = 0; kq < 16; kq++) {
    float4 b0 = *(const float4*)&Ws[(kq * 4 + 0) * 64 + tx * 4];
    float4 b1 = *(const float4*)&Ws[(kq * 4 + 1) * 64 + tx * 4];
    float4 b2 = *(const float4*)&Ws[(kq * 4 + 2) * 64 + tx * 4];
    float4 b3 = *(const float4*)&Ws[(kq * 4 + 3) * 64 + tx * 4];
#pragma unroll
    for (int r = 0; r < 4; r++) {
      float4 a = *(const float4*)&As[(ty * 4 + r) * 64 + kq * 4];
      MMA_ROW(acc[r], a);
    }
  }
  float4 bias = ((const float4*)b1m)[tx];
#pragma unroll
  for (int r = 0; r < 4; r++) {
    int n = n0 + ty * 4 + r;
    if (n < NN) {
      ((float4*)g_xw1)[(size_t)n * 16 + tx] =
          make_float4(acc[r][0] + bias.x, acc[r][1] + bias.y,
                      acc[r][2] + bias.z, acc[r][3] + bias.w);
    }
  }
}

// ---------------- edge GEMM: h1 = xw1[send] + ea @ w1m[64:128]; + BN stats --
__global__ __launch_bounds__(256) void k_edge(const float* __restrict__ ea,
                                              const int* __restrict__ send,
                                              const float* __restrict__ w1m) {
  __shared__ float As[128 * 64];   // 32 KB
  __shared__ float Ws[64 * 64];    // 16 KB (reused as stats buffer after GEMM)
  int e0 = blockIdx.x * 128;
  int tid = threadIdx.x;
  for (int i = tid; i < 64 * 16; i += 256) {
    int r = i >> 4, q = i & 15;
    *(float4*)&Ws[r * 64 + q * 4] = ((const float4*)w1m)[(64 + r) * 16 + q];
  }
  for (int i = tid; i < 128 * 16; i += 256) {
    int r = i >> 4, q = i & 15;
    *(float4*)&As[r * 64 + q * 4] = ((const float4*)ea)[(size_t)(e0 + r) * 16 + q];
  }
  __syncthreads();
  int tx = tid & 15, ty = tid >> 4;
  float acc[8][4] = {};
#pragma unroll 4
  for (int kq = 0; kq < 16; kq++) {
    float4 b0 = *(const float4*)&Ws[(kq * 4 + 0) * 64 + tx * 4];
    float4 b1 = *(const float4*)&Ws[(kq * 4 + 1) * 64 + tx * 4];
    float4 b2 = *(const float4*)&Ws[(kq * 4 + 2) * 64 + tx * 4];
    float4 b3 = *(const float4*)&Ws[(kq * 4 + 3) * 64 + tx * 4];
#pragma unroll
    for (int r = 0; r < 8; r++) {
      float4 a = *(const float4*)&As[(ty * 8 + r) * 64 + kq * 4];
      MMA_ROW(acc[r], a);
    }
  }
  __syncthreads();
  // gather xw1[send[e]] into As (Ws now dead -> stats buffer)
  float* sstats = Ws;
  if (tid < 128) sstats[tid] = 0.f;
  for (int i = tid; i < 128 * 16; i += 256) {
    int r = i >> 4, q = i & 15;
    int sn = __ldg(&send[e0 + r]);
    *(float4*)&As[r * 64 + q * 4] = ((const float4*)g_xw1)[(size_t)sn * 16 + q];
  }
  __syncthreads();
  float ps[4] = {0.f, 0.f, 0.f, 0.f}, pq2[4] = {0.f, 0.f, 0.f, 0.f};
#pragma unroll
  for (int r = 0; r < 8; r++) {
    float4 g = *(const float4*)&As[(ty * 8 + r) * 64 + tx * 4];
    float h0 = acc[r][0] + g.x;
    float h1v = acc[r][1] + g.y;
    float h2 = acc[r][2] + g.z;
    float h3 = acc[r][3] + g.w;
    ps[0] += h0; ps[1] += h1v; ps[2] += h2; ps[3] += h3;
    pq2[0] = fmaf(h0, h0, pq2[0]);
    pq2[1] = fmaf(h1v, h1v, pq2[1]);
    pq2[2] = fmaf(h2, h2, pq2[2]);
    pq2[3] = fmaf(h3, h3, pq2[3]);
    ((float4*)g_h1)[(size_t)(e0 + ty * 8 + r) * 16 + tx] = make_float4(h0, h1v, h2, h3);
  }
#pragma unroll
  for (int c = 0; c < 4; c++) {
    ps[c] += __shfl_down_sync(0xffffffffu, ps[c], 16);
    pq2[c] += __shfl_down_sync(0xffffffffu, pq2[c], 16);
  }
  if ((tid & 31) < 16) {
#pragma unroll
    for (int c = 0; c < 4; c++) {
      atomicAdd(&sstats[tx * 4 + c], ps[c]);
      atomicAdd(&sstats[64 + tx * 4 + c], pq2[c]);
    }
  }
  __syncthreads();
  if (tid < 128) atomicAdd(&g_estats[tid], sstats[tid]);
}

// ---------------- BN params from moments ----------------
__global__ void k_bn(const float* __restrict__ gamma, const float* __restrict__ beta,
                     float cinv, int which) {
  int j = threadIdx.x;
  const float* st = which ? g_nstats : g_estats;
  float mean = st[j] * cinv;
  float var = fmaxf(st[64 + j] * cinv - mean * mean, 0.f);
  float sc = gamma[j] * rsqrtf(var + EPSV);
  float sh = beta[j] - mean * sc;
  if (which) { g_nscale[j] = sc; g_nshift[j] = sh; }
  else       { g_escale[j] = sc; g_eshift[j] = sh; }
}

// ---------------- BN+ReLU+scatter-add (vector atomics) ----------------
__global__ __launch_bounds__(256) void k_scatter(const int* __restrict__ rec) {
  int gid = blockIdx.x * 256 + threadIdx.x;
  int e = gid >> 2, p = gid & 3;
  int r = __ldg(&rec[e]);
  const float4* src = (const float4*)(g_h1 + (size_t)e * 64);
  float4* dst = (float4*)(g_Sa + (size_t)r * 64);
#pragma unroll
  for (int i = 0; i < 4; i++) {
    int c4 = i * 4 + p;
    float4 v = src[c4];
    float4 sc = ((const float4*)g_escale)[c4];
    float4 sh = ((const float4*)g_eshift)[c4];
    float4 a;
    a.x = fmaxf(fmaf(v.x, sc.x, sh.x), 0.f);
    a.y = fmaxf(fmaf(v.y, sc.y, sh.y), 0.f);
    a.z = fmaxf(fmaf(v.z, sc.z, sh.z), 0.f);
    a.w = fmaxf(fmaf(v.w, sc.w, sh.w), 0.f);
    atomicAdd(dst + c4, a);
  }
  if (p == 0) atomicAdd(&g_cnt[r], 1.f);
}

// ---------------- node GEMM: h1n = [x | Sa/cnt] @ wcomb + b1n + gate*bc -----
__global__ __launch_bounds__(256) void k_node1(const float* __restrict__ x,
                                               const float* __restrict__ b1n) {
  __shared__ float As[64 * 136];   // K=128, padded stride 136 (16B aligned)
  __shared__ float Ws[32 * 64];
  __shared__ float scnt[64];
  __shared__ float sstats[128];
  int n0 = blockIdx.x * 64;
  int tid = threadIdx.x;
  if (tid < 64) {
    int n = n0 + tid;
    scnt[tid] = (n < NN) ? g_cnt[n] : 0.f;
  }
  if (tid >= 128) sstats[tid - 128] = 0.f;
  __syncthreads();
  for (int i = tid; i < 64 * 32; i += 256) {
    int r = i >> 5, q = i & 31;
    float4 v = make_float4(0.f, 0.f, 0.f, 0.f);
    int n = n0 + r;
    if (n < NN) {
      if (q < 16) v = ((const float4*)x)[(size_t)n * 16 + q];
      else {
        v = ((const float4*)g_Sa)[(size_t)n * 16 + (q - 16)];
        float inv = 1.f / fmaxf(scnt[r], 1.f);
        v.x *= inv; v.y *= inv; v.z *= inv; v.w *= inv;
      }
    }
    *(float4*)&As[r * 136 + q * 4] = v;
  }
  int tx = tid & 15, ty = tid >> 4;
  float acc[4][4] = {};
  for (int kc = 0; kc < 4; kc++) {
    __syncthreads();
    for (int i = tid; i < 32 * 16; i += 256) {
      int r = i >> 4, q = i & 15;
      *(float4*)&Ws[r * 64 + q * 4] = ((const float4*)g_wcomb)[(kc * 32 + r) * 16 + q];
    }
    __syncthreads();
#pragma unroll
    for (int kq = 0; kq < 8; kq++) {
      float4 b0 = *(const float4*)&Ws[(kq * 4 + 0) * 64 + tx * 4];
      float4 b1 = *(const float4*)&Ws[(kq * 4 + 1) * 64 + tx * 4];
      float4 b2 = *(const float4*)&Ws[(kq * 4 + 2) * 64 + tx * 4];
      float4 b3 = *(const float4*)&Ws[(kq * 4 + 3) * 64 + tx * 4];
#pragma unroll
      for (int r = 0; r < 4; r++) {
        float4 a = *(const float4*)&As[(ty * 4 + r) * 136 + kc * 32 + kq * 4];
        MMA_ROW(acc[r], a);
      }
    }
  }
  float4 bias = ((const float4*)b1n)[tx];
  float4 bcv = ((const float4*)g_bc)[tx];
  float ps[4] = {0.f, 0.f, 0.f, 0.f}, pq2[4] = {0.f, 0.f, 0.f, 0.f};
#pragma unroll
  for (int r = 0; r < 4; r++) {
    int row = ty * 4 + r, n = n0 + row;
    if (n < NN) {
      float gate = (scnt[row] > 0.f) ? 1.f : 0.f;
      float h0 = acc[r][0] + bias.x + gate * bcv.x;
      float h1v = acc[r][1] + bias.y + gate * bcv.y;
      float h2 = acc[r][2] + bias.z + gate * bcv.z;
      float h3 = acc[r][3] + bias.w + gate * bcv.w;
      ps[0] += h0; ps[1] += h1v; ps[2] += h2; ps[3] += h3;
      pq2[0] = fmaf(h0, h0, pq2[0]);
      pq2[1] = fmaf(h1v, h1v, pq2[1]);
      pq2[2] = fmaf(h2, h2, pq2[2]);
      pq2[3] = fmaf(h3, h3, pq2[3]);
      ((float4*)g_h1n)[(size_t)n * 16 + tx] = make_float4(h0, h1v, h2, h3);
    }
  }
#pragma unroll
  for (int c = 0; c < 4; c++) {
    ps[c] += __shfl_down_sync(0xffffffffu, ps[c], 16);
    pq2[c] += __shfl_down_sync(0xffffffffu, pq2[c], 16);
  }
  if ((tid & 31) < 16) {
#pragma unroll
    for (int c = 0; c < 4; c++) {
      atomicAdd(&sstats[tx * 4 + c], ps[c]);
      atomicAdd(&sstats[64 + tx * 4 + c], pq2[c]);
    }
  }
  __syncthreads();
  if (tid < 128) atomicAdd(&g_nstats[tid], sstats[tid]);
}

// ---------------- out = relu(bn(h1n)) @ w2n + b2n ----------------
__global__ __launch_bounds__(256) void k_out(const float* __restrict__ w2n,
                                             const float* __restrict__ b2n,
                                             float* __restrict__ out) {
  __shared__ float As[64 * 64];
  __shared__ float Ws[64 * 64];
  __shared__ float ssc[64], ssh[64];
  int n0 = blockIdx.x * 64;
  int tid = threadIdx.x;
  if (tid < 64) { ssc[tid] = g_nscale[tid]; ssh[tid] = g_nshift[tid]; }
  for (int i = tid; i < 64 * 16; i += 256) {
    int r = i >> 4, q = i & 15;
    *(float4*)&Ws[r * 64 + q * 4] = ((const float4*)w2n)[r * 16 + q];
  }
  __syncthreads();
  for (int i = tid; i < 64 * 16; i += 256) {
    int r = i >> 4, q = i & 15;
    float4 v = make_float4(0.f, 0.f, 0.f, 0.f);
    int n = n0 + r;
    if (n < NN) {
      v = ((const float4*)g_h1n)[(size_t)n * 16 + q];
      v.x = fmaxf(fmaf(v.x, ssc[q * 4 + 0], ssh[q * 4 + 0]), 0.f);
      v.y = fmaxf(fmaf(v.y, ssc[q * 4 + 1], ssh[q * 4 + 1]), 0.f);
      v.z = fmaxf(fmaf(v.z, ssc[q * 4 + 2], ssh[q * 4 + 2]), 0.f);
      v.w = fmaxf(fmaf(v.w, ssc[q * 4 + 3], ssh[q * 4 + 3]), 0.f);
    }
    *(float4*)&As[r * 64 + q * 4] = v;
  }
  __syncthreads();
  int tx = tid & 15, ty = tid >> 4;
  float acc[4][4] = {};
#pragma unroll 4
  for (int kq = 0; kq < 16; kq++) {
    float4 b0 = *(const float4*)&Ws[(kq * 4 + 0) * 64 + tx * 4];
    float4 b1 = *(const float4*)&Ws[(kq * 4 + 1) * 64 + tx * 4];
    float4 b2 = *(const float4*)&Ws[(kq * 4 + 2) * 64 + tx * 4];
    float4 b3 = *(const float4*)&Ws[(kq * 4 + 3) * 64 + tx * 4];
#pragma unroll
    for (int r = 0; r < 4; r++) {
      float4 a = *(const float4*)&As[(ty * 4 + r) * 64 + kq * 4];
      MMA_ROW(acc[r], a);
    }
  }
  float4 bias = ((const float4*)b2n)[tx];
#pragma unroll
  for (int r = 0; r < 4; r++) {
    int n = n0 + ty * 4 + r;
    if (n < NN) {
      ((float4*)out)[(size_t)n * 16 + tx] =
          make_float4(acc[r][0] + bias.x, acc[r][1] + bias.y,
                      acc[r][2] + bias.z, acc[r][3] + bias.w);
    }
  }
}

extern "C" void kernel_launch(void* const* d_in, const int* in_sizes, int n_in,
                              void* d_out, int out_size) {
  const float* x   = (const float*)d_in[0];
  const int*   ei  = (const int*)d_in[1];   // [2,E]: send = ei, rec = ei+E
  const float* ea  = (const float*)d_in[2];
  const float* w1m = (const float*)d_in[5];
  const float* b1m = (const float*)d_in[6];
  const float* gm  = (const float*)d_in[7];
  const float* bm  = (const float*)d_in[8];
  const float* w2m = (const float*)d_in[9];
  const float* b2m = (const float*)d_in[10];
  const float* w1n = (const float*)d_in[11];
  const float* b1n = (const float*)d_in[12];
  const float* gn  = (const float*)d_in[13];
  const float* bnb = (const float*)d_in[14];
  const float* w2n = (const float*)d_in[15];
  const float* b2n = (const float*)d_in[16];
  float* out = (float*)d_out;

  const int zero_total = NN * 64 + NN + 256;
  k_zero<<<(zero_total + 255) / 256, 256>>>();
  k_wprep<<<16, 256>>>(w1n, w2m, b2m);
  k_xw1<<<(NN + 63) / 64, 256>>>(x, w1m, b1m);
  k_edge<<<NE / 128, 256>>>(ea, ei, w1m);
  k_bn<<<1, 64>>>(gm, bm, 1.f / (float)NE, 0);
  k_scatter<<<NE * 4 / 256, 256>>>(ei + NE);
  k_node1<<<(NN + 63) / 64, 256>>>(x, b1n);
  k_bn<<<1, 64>>>(gn, bnb, 1.f / (float)NN, 1);
  k_out<<<(NN + 63) / 64, 256>>>(w2n, b2n, out);
}

// round 2
// speedup vs baseline: 1.1421x; 1.1421x over previous
#include <cuda_runtime.h>
#include <cuda_fp16.h>
#include <math.h>

#define NN 50000
#define NE 800000
#define EPSV 1e-5f

// ---------------- scratch (static __device__, no allocation) ----------------
__device__ __align__(16) uint2 g_h1[NE * 16];      // [E,64] pre-BN edge hidden, fp16x4 per uint2 (102MB)
__device__ __align__(16) float g_xw1[NN * 64];     // x @ w1m_top + b1m
__device__ __align__(16) float g_Sa[NN * 64];      // scatter-sum of relu(bn(h1))
__device__ __align__(16) float g_cnt[NN];
__device__ __align__(16) float g_h1n[NN * 64];     // pre-BN node hidden
__device__ __align__(16) float g_wcomb[128 * 64];  // [w1n_top ; w2m@w1n_bot]
__device__ __align__(16) float g_bc[64];           // b2m @ w1n_bot
__device__ __align__(16) float g_estats[128];      // sum | sumsq (edge BN)
__device__ __align__(16) float g_nstats[128];      // sum | sumsq (node BN)
__device__ __align__(16) float g_escale[64];
__device__ __align__(16) float g_eshift[64];
__device__ __align__(16) float g_nscale[64];
__device__ __align__(16) float g_nshift[64];

#define MMA_ROW(ar, a) do { \
  ar[0]=fmaf(a.x,b0.x,ar[0]); ar[0]=fmaf(a.y,b1.x,ar[0]); ar[0]=fmaf(a.z,b2.x,ar[0]); ar[0]=fmaf(a.w,b3.x,ar[0]); \
  ar[1]=fmaf(a.x,b0.y,ar[1]); ar[1]=fmaf(a.y,b1.y,ar[1]); ar[1]=fmaf(a.z,b2.y,ar[1]); ar[1]=fmaf(a.w,b3.y,ar[1]); \
  ar[2]=fmaf(a.x,b0.z,ar[2]); ar[2]=fmaf(a.y,b1.z,ar[2]); ar[2]=fmaf(a.z,b2.z,ar[2]); ar[2]=fmaf(a.w,b3.z,ar[2]); \
  ar[3]=fmaf(a.x,b0.w,ar[3]); ar[3]=fmaf(a.y,b1.w,ar[3]); ar[3]=fmaf(a.z,b2.w,ar[3]); ar[3]=fmaf(a.w,b3.w,ar[3]); \
} while(0)

// ---------------- zero accumulators ----------------
__global__ void k_zero() {
  size_t i = (size_t)blockIdx.x * 256 + threadIdx.x;
  const size_t nsa = (size_t)NN * 64;
  if (i < nsa) { g_Sa[i] = 0.f; return; }
  i -= nsa;
  if (i < NN) { g_cnt[i] = 0.f; return; }
  i -= NN;
  if (i < 128) { g_estats[i] = 0.f; return; }
  i -= 128;
  if (i < 128) { g_nstats[i] = 0.f; return; }
}

// ---------------- fold w2m into w1n_bot: wcomb = [w1n_top ; w2m@w1n_bot] ----
__global__ void k_wprep(const float* __restrict__ w1n, const float* __restrict__ w2m,
                        const float* __restrict__ b2m) {
  int b = blockIdx.x, t = threadIdx.x;     // 16 blocks x 256 threads
  g_wcomb[b * 256 + t] = w1n[b * 256 + t]; // copy top 64 rows (4096 entries)
  int k = b * 4 + (t >> 6), j = t & 63;    // Wc[k][j]
  float s = 0.f;
  for (int q = 0; q < 64; q++) s = fmaf(w2m[k * 64 + q], w1n[(64 + q) * 64 + j], s);
  g_wcomb[(64 + k) * 64 + j] = s;
  if (b == 0 && t < 64) {
    float sb = 0.f;
    for (int q = 0; q < 64; q++) sb = fmaf(b2m[q], w1n[(64 + q) * 64 + t], sb);
    g_bc[t] = sb;
  }
}

// ---------------- xw1 = x @ w1m[0:64] + b1m ----------------
__global__ __launch_bounds__(256) void k_xw1(const float* __restrict__ x,
                                             const float* __restrict__ w1m,
                                             const float* __restrict__ b1m) {
  __shared__ float As[64 * 64];
  __shared__ float Ws[64 * 64];
  int n0 = blockIdx.x * 64;
  int tid = threadIdx.x;
  for (int i = tid; i < 64 * 16; i += 256) {
    int r = i >> 4, q = i & 15;
    *(float4*)&Ws[r * 64 + q * 4] = ((const float4*)w1m)[r * 16 + q];
  }
  for (int i = tid; i < 64 * 16; i += 256) {
    int r = i >> 4, q = i & 15;
    float4 v = make_float4(0.f, 0.f, 0.f, 0.f);
    if (n0 + r < NN) v = ((const float4*)x)[(size_t)(n0 + r) * 16 + q];
    *(float4*)&As[r * 64 + q * 4] = v;
  }
  __syncthreads();
  int tx = tid & 15, ty = tid >> 4;
  float acc[4][4] = {};
#pragma unroll 4
  for (int kq = 0; kq < 16; kq++) {
    float4 b0 = *(const float4*)&Ws[(kq * 4 + 0) * 64 + tx * 4];
    float4 b1 = *(const float4*)&Ws[(kq * 4 + 1) * 64 + tx * 4];
    float4 b2 = *(const float4*)&Ws[(kq * 4 + 2) * 64 + tx * 4];
    float4 b3 = *(const float4*)&Ws[(kq * 4 + 3) * 64 + tx * 4];
#pragma unroll
    for (int r = 0; r < 4; r++) {
      float4 a = *(const float4*)&As[(ty * 4 + r) * 64 + kq * 4];
      MMA_ROW(acc[r], a);
    }
  }
  float4 bias = ((const float4*)b1m)[tx];
#pragma unroll
  for (int r = 0; r < 4; r++) {
    int n = n0 + ty * 4 + r;
    if (n < NN) {
      ((float4*)g_xw1)[(size_t)n * 16 + tx] =
          make_float4(acc[r][0] + bias.x, acc[r][1] + bias.y,
                      acc[r][2] + bias.z, acc[r][3] + bias.w);
    }
  }
}

// ---------------- edge GEMM: h1 = xw1[send] + ea @ w1m[64:128]; + BN stats --
// Per-thread register-direct gather of xw1 (no smem re-stage), fp16 h1 store.
__global__ __launch_bounds__(256, 3) void k_edge(const float* __restrict__ ea,
                                                 const int* __restrict__ send,
                                                 const float* __restrict__ w1m) {
  __shared__ float As[128 * 64];   // 32 KB
  __shared__ float Ws[64 * 64];    // 16 KB (reused as stats buffer after GEMM)
  int e0 = blockIdx.x * 128;
  int tid = threadIdx.x;
  for (int i = tid; i < 64 * 16; i += 256) {
    int r = i >> 4, q = i & 15;
    *(float4*)&Ws[r * 64 + q * 4] = ((const float4*)w1m)[(64 + r) * 16 + q];
  }
  for (int i = tid; i < 128 * 16; i += 256) {
    int r = i >> 4, q = i & 15;
    *(float4*)&As[r * 64 + q * 4] = ((const float4*)ea)[(size_t)(e0 + r) * 16 + q];
  }
  __syncthreads();
  int tx = tid & 15, ty = tid >> 4;
  float acc[8][4] = {};
#pragma unroll 4
  for (int kq = 0; kq < 16; kq++) {
    float4 b0 = *(const float4*)&Ws[(kq * 4 + 0) * 64 + tx * 4];
    float4 b1 = *(const float4*)&Ws[(kq * 4 + 1) * 64 + tx * 4];
    float4 b2 = *(const float4*)&Ws[(kq * 4 + 2) * 64 + tx * 4];
    float4 b3 = *(const float4*)&Ws[(kq * 4 + 3) * 64 + tx * 4];
#pragma unroll
    for (int r = 0; r < 8; r++) {
      float4 a = *(const float4*)&As[(ty * 8 + r) * 64 + kq * 4];
      MMA_ROW(acc[r], a);
    }
  }
  __syncthreads();                 // all warps done with Ws -> reuse as stats
  float* sstats = Ws;
  if (tid < 128) sstats[tid] = 0.f;
  // epilogue: per-thread direct gather of xw1[send], stats, fp16 store
  float ps[4] = {0.f, 0.f, 0.f, 0.f}, pq2[4] = {0.f, 0.f, 0.f, 0.f};
#pragma unroll
  for (int r = 0; r < 8; r++) {
    int row = ty * 8 + r;
    int sn = __ldg(&send[e0 + row]);
    float4 g = __ldg(&((const float4*)g_xw1)[(size_t)sn * 16 + tx]);
    float h0 = acc[r][0] + g.x;
    float h1v = acc[r][1] + g.y;
    float h2 = acc[r][2] + g.z;
    float h3 = acc[r][3] + g.w;
    ps[0] += h0; ps[1] += h1v; ps[2] += h2; ps[3] += h3;
    pq2[0] = fmaf(h0, h0, pq2[0]);
    pq2[1] = fmaf(h1v, h1v, pq2[1]);
    pq2[2] = fmaf(h2, h2, pq2[2]);
    pq2[3] = fmaf(h3, h3, pq2[3]);
    uint2 u;
    __half2 lo = __floats2half2_rn(h0, h1v);
    __half2 hi = __floats2half2_rn(h2, h3);
    u.x = *(unsigned int*)&lo;
    u.y = *(unsigned int*)&hi;
    g_h1[(size_t)(e0 + row) * 16 + tx] = u;
  }
#pragma unroll
  for (int c = 0; c < 4; c++) {
    ps[c] += __shfl_down_sync(0xffffffffu, ps[c], 16);
    pq2[c] += __shfl_down_sync(0xffffffffu, pq2[c], 16);
  }
  __syncthreads();                 // sstats zeroing visible to all warps
  if ((tid & 31) < 16) {
#pragma unroll
    for (int c = 0; c < 4; c++) {
      atomicAdd(&sstats[tx * 4 + c], ps[c]);
      atomicAdd(&sstats[64 + tx * 4 + c], pq2[c]);
    }
  }
  __syncthreads();
  if (tid < 128) atomicAdd(&g_estats[tid], sstats[tid]);
}

// ---------------- BN params from moments ----------------
__global__ void k_bn(const float* __restrict__ gamma, const float* __restrict__ beta,
                     float cinv, int which) {
  int j = threadIdx.x;
  const float* st = which ? g_nstats : g_estats;
  float mean = st[j] * cinv;
  float var = fmaxf(st[64 + j] * cinv - mean * mean, 0.f);
  float sc = gamma[j] * rsqrtf(var + EPSV);
  float sh = beta[j] - mean * sc;
  if (which) { g_nscale[j] = sc; g_nshift[j] = sh; }
  else       { g_escale[j] = sc; g_eshift[j] = sh; }
}

// ---------------- BN+ReLU+scatter-add (fp16 read, vector fp32 atomics) -----
__global__ __launch_bounds__(256) void k_scatter(const int* __restrict__ rec) {
  int gid = blockIdx.x * 256 + threadIdx.x;
  int e = gid >> 2, p = gid & 3;
  int r = __ldg(&rec[e]);
  float4* dst = (float4*)(g_Sa + (size_t)r * 64);
#pragma unroll
  for (int k = 0; k < 4; k++) {
    int c4 = p * 4 + k;                    // which group of 4 columns
    uint2 u = g_h1[(size_t)e * 16 + c4];
    __half2 lo = *(__half2*)&u.x;
    __half2 hi = *(__half2*)&u.y;
    float2 f0 = __half22float2(lo);
    float2 f1 = __half22float2(hi);
    float4 sc = ((const float4*)g_escale)[c4];
    float4 sh = ((const float4*)g_eshift)[c4];
    float4 a;
    a.x = fmaxf(fmaf(f0.x, sc.x, sh.x), 0.f);
    a.y = fmaxf(fmaf(f0.y, sc.y, sh.y), 0.f);
    a.z = fmaxf(fmaf(f1.x, sc.z, sh.z), 0.f);
    a.w = fmaxf(fmaf(f1.y, sc.w, sh.w), 0.f);
    atomicAdd(dst + c4, a);
  }
  if (p == 0) atomicAdd(&g_cnt[r], 1.f);
}

// ---------------- node GEMM: h1n = [x | Sa/cnt] @ wcomb + b1n + gate*bc -----
__global__ __launch_bounds__(256) void k_node1(const float* __restrict__ x,
                                               const float* __restrict__ b1n) {
  __shared__ float As[64 * 136];   // K=128, padded stride 136 (16B aligned)
  __shared__ float Ws[32 * 64];
  __shared__ float scnt[64];
  __shared__ float sstats[128];
  int n0 = blockIdx.x * 64;
  int tid = threadIdx.x;
  if (tid < 64) {
    int n = n0 + tid;
    scnt[tid] = (n < NN) ? g_cnt[n] : 0.f;
  }
  if (tid >= 128) sstats[tid - 128] = 0.f;
  __syncthreads();
  for (int i = tid; i < 64 * 32; i += 256) {
    int r = i >> 5, q = i & 31;
    float4 v = make_float4(0.f, 0.f, 0.f, 0.f);
    int n = n0 + r;
    if (n < NN) {
      if (q < 16) v = ((const float4*)x)[(size_t)n * 16 + q];
      else {
        v = ((const float4*)g_Sa)[(size_t)n * 16 + (q - 16)];
        float inv = 1.f / fmaxf(scnt[r], 1.f);
        v.x *= inv; v.y *= inv; v.z *= inv; v.w *= inv;
      }
    }
    *(float4*)&As[r * 136 + q * 4] = v;
  }
  int tx = tid & 15, ty = tid >> 4;
  float acc[4][4] = {};
  for (int kc = 0; kc < 4; kc++) {
    __syncthreads();
    for (int i = tid; i < 32 * 16; i += 256) {
      int r = i >> 4, q = i & 15;
      *(float4*)&Ws[r * 64 + q * 4] = ((const float4*)g_wcomb)[(kc * 32 + r) * 16 + q];
    }
    __syncthreads();
#pragma unroll
    for (int kq = 0; kq < 8; kq++) {
      float4 b0 = *(const float4*)&Ws[(kq * 4 + 0) * 64 + tx * 4];
      float4 b1 = *(const float4*)&Ws[(kq * 4 + 1) * 64 + tx * 4];
      float4 b2 = *(const float4*)&Ws[(kq * 4 + 2) * 64 + tx * 4];
      float4 b3 = *(const float4*)&Ws[(kq * 4 + 3) * 64 + tx * 4];
#pragma unroll
      for (int r = 0; r < 4; r++) {
        float4 a = *(const float4*)&As[(ty * 4 + r) * 136 + kc * 32 + kq * 4];
        MMA_ROW(acc[r], a);
      }
    }
  }
  float4 bias = ((const float4*)b1n)[tx];
  float4 bcv = ((const float4*)g_bc)[tx];
  float ps[4] = {0.f, 0.f, 0.f, 0.f}, pq2[4] = {0.f, 0.f, 0.f, 0.f};
#pragma unroll
  for (int r = 0; r < 4; r++) {
    int row = ty * 4 + r, n = n0 + row;
    if (n < NN) {
      float gate = (scnt[row] > 0.f) ? 1.f : 0.f;
      float h0 = acc[r][0] + bias.x + gate * bcv.x;
      float h1v = acc[r][1] + bias.y + gate * bcv.y;
      float h2 = acc[r][2] + bias.z + gate * bcv.z;
      float h3 = acc[r][3] + bias.w + gate * bcv.w;
      ps[0] += h0; ps[1] += h1v; ps[2] += h2; ps[3] += h3;
      pq2[0] = fmaf(h0, h0, pq2[0]);
      pq2[1] = fmaf(h1v, h1v, pq2[1]);
      pq2[2] = fmaf(h2, h2, pq2[2]);
      pq2[3] = fmaf(h3, h3, pq2[3]);
      ((float4*)g_h1n)[(size_t)n * 16 + tx] = make_float4(h0, h1v, h2, h3);
    }
  }
#pragma unroll
  for (int c = 0; c < 4; c++) {
    ps[c] += __shfl_down_sync(0xffffffffu, ps[c], 16);
    pq2[c] += __shfl_down_sync(0xffffffffu, pq2[c], 16);
  }
  if ((tid & 31) < 16) {
#pragma unroll
    for (int c = 0; c < 4; c++) {
      atomicAdd(&sstats[tx * 4 + c], ps[c]);
      atomicAdd(&sstats[64 + tx * 4 + c], pq2[c]);
    }
  }
  __syncthreads();
  if (tid < 128) atomicAdd(&g_nstats[tid], sstats[tid]);
}

// ---------------- out = relu(bn(h1n)) @ w2n + b2n ----------------
__global__ __launch_bounds__(256) void k_out(const float* __restrict__ w2n,
                                             const float* __restrict__ b2n,
                                             float* __restrict__ out) {
  __shared__ float As[64 * 64];
  __shared__ float Ws[64 * 64];
  __shared__ float ssc[64], ssh[64];
  int n0 = blockIdx.x * 64;
  int tid = threadIdx.x;
  if (tid < 64) { ssc[tid] = g_nscale[tid]; ssh[tid] = g_nshift[tid]; }
  for (int i = tid; i < 64 * 16; i += 256) {
    int r = i >> 4, q = i & 15;
    *(float4*)&Ws[r * 64 + q * 4] = ((const float4*)w2n)[r * 16 + q];
  }
  __syncthreads();
  for (int i = tid; i < 64 * 16; i += 256) {
    int r = i >> 4, q = i & 15;
    float4 v = make_float4(0.f, 0.f, 0.f, 0.f);
    int n = n0 + r;
    if (n < NN) {
      v = ((const float4*)g_h1n)[(size_t)n * 16 + q];
      v.x = fmaxf(fmaf(v.x, ssc[q * 4 + 0], ssh[q * 4 + 0]), 0.f);
      v.y = fmaxf(fmaf(v.y, ssc[q * 4 + 1], ssh[q * 4 + 1]), 0.f);
      v.z = fmaxf(fmaf(v.z, ssc[q * 4 + 2], ssh[q * 4 + 2]), 0.f);
      v.w = fmaxf(fmaf(v.w, ssc[q * 4 + 3], ssh[q * 4 + 3]), 0.f);
    }
    *(float4*)&As[r * 64 + q * 4] = v;
  }
  __syncthreads();
  int tx = tid & 15, ty = tid >> 4;
  float acc[4][4] = {};
#pragma unroll 4
  for (int kq = 0; kq < 16; kq++) {
    float4 b0 = *(const float4*)&Ws[(kq * 4 + 0) * 64 + tx * 4];
    float4 b1 = *(const float4*)&Ws[(kq * 4 + 1) * 64 + tx * 4];
    float4 b2 = *(const float4*)&Ws[(kq * 4 + 2) * 64 + tx * 4];
    float4 b3 = *(const float4*)&Ws[(kq * 4 + 3) * 64 + tx * 4];
#pragma unroll
    for (int r = 0; r < 4; r++) {
      float4 a = *(const float4*)&As[(ty * 4 + r) * 64 + kq * 4];
      MMA_ROW(acc[r], a);
    }
  }
  float4 bias = ((const float4*)b2n)[tx];
#pragma unroll
  for (int r = 0; r < 4; r++) {
    int n = n0 + ty * 4 + r;
    if (n < NN) {
      ((float4*)out)[(size_t)n * 16 + tx] =
          make_float4(acc[r][0] + bias.x, acc[r][1] + bias.y,
                      acc[r][2] + bias.z, acc[r][3] + bias.w);
    }
  }
}

extern "C" void kernel_launch(void* const* d_in, const int* in_sizes, int n_in,
                              void* d_out, int out_size) {
  const float* x   = (const float*)d_in[0];
  const int*   ei  = (const int*)d_in[1];   // [2,E]: send = ei, rec = ei+E
  const float* ea  = (const float*)d_in[2];
  const float* w1m = (const float*)d_in[5];
  const float* b1m = (const float*)d_in[6];
  const float* gm  = (const float*)d_in[7];
  const float* bm  = (const float*)d_in[8];
  const float* w2m = (const float*)d_in[9];
  const float* b2m = (const float*)d_in[10];
  const float* w1n = (const float*)d_in[11];
  const float* b1n = (const float*)d_in[12];
  const float* gn  = (const float*)d_in[13];
  const float* bnb = (const float*)d_in[14];
  const float* w2n = (const float*)d_in[15];
  const float* b2n = (const float*)d_in[16];
  float* out = (float*)d_out;

  const int zero_total = NN * 64 + NN + 256;
  k_zero<<<(zero_total + 255) / 256, 256>>>();
  k_wprep<<<16, 256>>>(w1n, w2m, b2m);
  k_xw1<<<(NN + 63) / 64, 256>>>(x, w1m, b1m);
  k_edge<<<NE / 128, 256>>>(ea, ei, w1m);
  k_bn<<<1, 64>>>(gm, bm, 1.f / (float)NE, 0);
  k_scatter<<<NE * 4 / 256, 256>>>(ei + NE);
  k_node1<<<(NN + 63) / 64, 256>>>(x, b1n);
  k_bn<<<1, 64>>>(gn, bnb, 1.f / (float)NN, 1);
  k_out<<<(NN + 63) / 64, 256>>>(w2n, b2n, out);
}

// round 4
// speedup vs baseline: 1.7652x; 1.5456x over previous
#include <cuda_runtime.h>
#include <cuda_fp16.h>
#include <math.h>
#include <cstdint>

#define NN 50000
#define NE 800000
#define EPSV 1e-5f

// ---------------- scratch (static __device__, no allocation) ----------------
__device__ __align__(16) uint2 g_h1[NE * 16];      // [E,64] pre-BN edge hidden, fp16x4 per uint2 (102MB)
__device__ __align__(16) float g_xw1[NN * 64];     // x @ w1m_top + b1m
__device__ __align__(16) float g_Sa[NN * 64];      // scatter-sum of relu(bn(h1))
__device__ __align__(16) float g_cnt[NN];
__device__ __align__(16) float g_h1n[NN * 64];     // pre-BN node hidden
__device__ __align__(16) float g_wcomb[128 * 64];  // [w1n_top ; w2m@w1n_bot]
__device__ __align__(16) float g_bc[64];           // b2m @ w1n_bot
__device__ __align__(16) float g_estats[128];      // sum | sumsq (edge BN)
__device__ __align__(16) float g_nstats[128];      // sum | sumsq (node BN)
__device__ __align__(16) float g_escale[64];
__device__ __align__(16) float g_eshift[64];
__device__ __align__(16) float g_nscale[64];
__device__ __align__(16) float g_nshift[64];
__device__ __align__(16) uint4 g_Wt16[512];        // W_bot^T fp16, SW128-preswizzled (8KB)

__device__ __forceinline__ uint32_t smem_u32(const void* p) {
  uint32_t a;
  asm("{ .reg .u64 t; cvta.to.shared.u64 t, %1; cvt.u32.u64 %0, t; }" : "=r"(a) : "l"(p));
  return a;
}
#define SWZ128(b) ((b) ^ (((b) >> 3) & 0x70))

#define LDSM_X4(r0, r1, r2, r3, addr) \
  asm volatile("ldmatrix.sync.aligned.m8n8.x4.shared.b16 {%0,%1,%2,%3}, [%4];" \
    : "=r"(r0), "=r"(r1), "=r"(r2), "=r"(r3) : "r"(addr))

#define HMMA(d, a0, a1, a2, a3, b0, b1) \
  asm volatile("mma.sync.aligned.m16n8k16.row.col.f32.f16.f16.f32 " \
    "{%0,%1,%2,%3}, {%4,%5,%6,%7}, {%8,%9}, {%0,%1,%2,%3};" \
    : "+f"((d)[0]), "+f"((d)[1]), "+f"((d)[2]), "+f"((d)[3]) \
    : "r"(a0), "r"(a1), "r"(a2), "r"(a3), "r"(b0), "r"(b1))

#define MMA_ROW(ar, a) do { \
  ar[0]=fmaf(a.x,b0.x,ar[0]); ar[0]=fmaf(a.y,b1.x,ar[0]); ar[0]=fmaf(a.z,b2.x,ar[0]); ar[0]=fmaf(a.w,b3.x,ar[0]); \
  ar[1]=fmaf(a.x,b0.y,ar[1]); ar[1]=fmaf(a.y,b1.y,ar[1]); ar[1]=fmaf(a.z,b2.y,ar[1]); ar[1]=fmaf(a.w,b3.y,ar[1]); \
  ar[2]=fmaf(a.x,b0.z,ar[2]); ar[2]=fmaf(a.y,b1.z,ar[2]); ar[2]=fmaf(a.z,b2.z,ar[2]); ar[2]=fmaf(a.w,b3.z,ar[2]); \
  ar[3]=fmaf(a.x,b0.w,ar[3]); ar[3]=fmaf(a.y,b1.w,ar[3]); ar[3]=fmaf(a.z,b2.w,ar[3]); ar[3]=fmaf(a.w,b3.w,ar[3]); \
} while(0)

// ---------------- zero accumulators ----------------
__global__ void k_zero() {
  size_t i = (size_t)blockIdx.x * 256 + threadIdx.x;
  const size_t nsa = (size_t)NN * 64;
  if (i < nsa) { g_Sa[i] = 0.f; return; }
  i -= nsa;
  if (i < NN) { g_cnt[i] = 0.f; return; }
  i -= NN;
  if (i < 128) { g_estats[i] = 0.f; return; }
  i -= 128;
  if (i < 128) { g_nstats[i] = 0.f; return; }
}

// ---- fold w2m into w1n_bot; also build fp16 SW128-preswizzled W_bot^T ------
__global__ void k_wprep(const float* __restrict__ w1n, const float* __restrict__ w2m,
                        const float* __restrict__ b2m, const float* __restrict__ w1m) {
  int b = blockIdx.x, t = threadIdx.x;     // 16 blocks x 256 threads
  g_wcomb[b * 256 + t] = w1n[b * 256 + t]; // copy top 64 rows (4096 entries)
  int k = b * 4 + (t >> 6), j = t & 63;    // Wc[k][j]
  float s = 0.f;
  for (int q = 0; q < 64; q++) s = fmaf(w2m[k * 64 + q], w1n[(64 + q) * 64 + j], s);
  g_wcomb[(64 + k) * 64 + j] = s;
  if (b == 0 && t < 64) {
    float sb = 0.f;
    for (int q = 0; q < 64; q++) sb = fmaf(b2m[q], w1n[(64 + q) * 64 + t], sb);
    g_bc[t] = sb;
  }
  // Wt16[n][kk] = w1m[64+kk][n], fp16, SW128 swizzled (row = 64 halfs = 128B)
  int idx = b * 256 + t;                   // 0..4095
  int n = idx >> 6, kk = idx & 63;
  __half hv = __float2half(w1m[(64 + kk) * 64 + n]);
  unsigned off = SWZ128((unsigned)(n * 128 + kk * 2));
  ((__half*)g_Wt16)[off >> 1] = hv;
}

// ---------------- xw1 = x @ w1m[0:64] + b1m ----------------
__global__ __launch_bounds__(256) void k_xw1(const float* __restrict__ x,
                                             const float* __restrict__ w1m,
                                             const float* __restrict__ b1m) {
  __shared__ float As[64 * 64];
  __shared__ float Ws[64 * 64];
  int n0 = blockIdx.x * 64;
  int tid = threadIdx.x;
  for (int i = tid; i < 64 * 16; i += 256) {
    int r = i >> 4, q = i & 15;
    *(float4*)&Ws[r * 64 + q * 4] = ((const float4*)w1m)[r * 16 + q];
  }
  for (int i = tid; i < 64 * 16; i += 256) {
    int r = i >> 4, q = i & 15;
    float4 v = make_float4(0.f, 0.f, 0.f, 0.f);
    if (n0 + r < NN) v = ((const float4*)x)[(size_t)(n0 + r) * 16 + q];
    *(float4*)&As[r * 64 + q * 4] = v;
  }
  __syncthreads();
  int tx = tid & 15, ty = tid >> 4;
  float acc[4][4] = {};
#pragma unroll 4
  for (int kq = 0; kq < 16; kq++) {
    float4 b0 = *(const float4*)&Ws[(kq * 4 + 0) * 64 + tx * 4];
    float4 b1 = *(const float4*)&Ws[(kq * 4 + 1) * 64 + tx * 4];
    float4 b2 = *(const float4*)&Ws[(kq * 4 + 2) * 64 + tx * 4];
    float4 b3 = *(const float4*)&Ws[(kq * 4 + 3) * 64 + tx * 4];
#pragma unroll
    for (int r = 0; r < 4; r++) {
      float4 a = *(const float4*)&As[(ty * 4 + r) * 64 + kq * 4];
      MMA_ROW(acc[r], a);
    }
  }
  float4 bias = ((const float4*)b1m)[tx];
#pragma unroll
  for (int r = 0; r < 4; r++) {
    int n = n0 + ty * 4 + r;
    if (n < NN) {
      ((float4*)g_xw1)[(size_t)n * 16 + tx] =
          make_float4(acc[r][0] + bias.x, acc[r][1] + bias.y,
                      acc[r][2] + bias.z, acc[r][3] + bias.w);
    }
  }
}

// ------- edge: HMMA (mma.sync m16n8k16) for ea @ w1m_bot, + gather/stats ----
// static smem: stats [0,512), A fp16 swz [512,16896), B fp16 swz [16896,26112),
// D fp32 overlaps A/B at [512, 512+128*72*4=37376)
#define ESM_TOTAL 37376
__global__ __launch_bounds__(256, 4) void k_edge(const float* __restrict__ ea,
                                                 const int* __restrict__ send) {
  __shared__ __align__(16) char sm[ESM_TOTAL];
  float* sstats = (float*)sm;
  char* Asm = sm + 512;
  char* Bsm = sm + 16896;
  float* Dsm = (float*)(sm + 512);
  int tid = threadIdx.x, w = tid >> 5, L = tid & 31;
  int e0 = blockIdx.x * 128;

  if (tid < 128) sstats[tid] = 0.f;
  // stage A: ea[128 x 64] fp32 -> fp16 SW128-swizzled
  for (int i = tid; i < 1024; i += 256) {
    int r = i >> 3, q = i & 7;
    float4 f0 = ((const float4*)ea)[(size_t)(e0 + r) * 16 + q * 2];
    float4 f1 = ((const float4*)ea)[(size_t)(e0 + r) * 16 + q * 2 + 1];
    __half2 h01 = __floats2half2_rn(f0.x, f0.y);
    __half2 h23 = __floats2half2_rn(f0.z, f0.w);
    __half2 h45 = __floats2half2_rn(f1.x, f1.y);
    __half2 h67 = __floats2half2_rn(f1.z, f1.w);
    uint4 u;
    u.x = *(unsigned*)&h01; u.y = *(unsigned*)&h23;
    u.z = *(unsigned*)&h45; u.w = *(unsigned*)&h67;
    unsigned off = SWZ128((unsigned)(r * 128 + q * 16));
    *(uint4*)(Asm + off) = u;
  }
  // stage B: preswizzled fp16 W_bot^T (8KB)
  ((uint4*)Bsm)[tid] = g_Wt16[tid];
  ((uint4*)Bsm)[tid + 256] = g_Wt16[tid + 256];
  __syncthreads();

  // HMMA: warp w computes rows [w*16, w*16+16) x all 64 cols
  uint32_t sb_a = smem_u32(Asm), sb_b = smem_u32(Bsm);
  float acc[8][4] = {};
  unsigned arow = w * 16 + (L & 15);
  unsigned nrow = (L & 7) + ((L >> 4) << 3);  // B ldmatrix n within 16-row pair
  unsigned bkoff = (L >> 3) & 1;              // B ldmatrix col-block parity
#pragma unroll
  for (int kk8 = 0; kk8 < 8; kk8 += 2) {      // k-step of 16 = 2 col blocks
    unsigned acb = kk8 + (L >> 4);
    uint32_t aaddr = sb_a + arow * 128 + ((acb ^ (arow & 7)) << 4);
    uint32_t a0, a1, a2, a3;
    LDSM_X4(a0, a1, a2, a3, aaddr);
#pragma unroll
    for (int t = 0; t < 4; t++) {             // two 8-col n-tiles per iter
      unsigned n = t * 16 + nrow;
      unsigned bcb = kk8 + bkoff;
      uint32_t baddr = sb_b + n * 128 + ((bcb ^ (n & 7)) << 4);
      uint32_t b0, b1, b2, b3;
      LDSM_X4(b0, b1, b2, b3, baddr);
      HMMA(acc[2 * t], a0, a1, a2, a3, b0, b1);
      HMMA(acc[2 * t + 1], a0, a1, a2, a3, b2, b3);
    }
  }
  __syncthreads();                            // A/B dead -> D restage
  {
    int g = L >> 2, c = L & 3;
    int row0 = w * 16 + g, row1 = row0 + 8;
#pragma unroll
    for (int t = 0; t < 8; t++) {
      *(float2*)&Dsm[row0 * 72 + t * 8 + 2 * c] = make_float2(acc[t][0], acc[t][1]);
      *(float2*)&Dsm[row1 * 72 + t * 8 + 2 * c] = make_float2(acc[t][2], acc[t][3]);
    }
  }
  __syncthreads();

  // epilogue: gather xw1[send], stats, fp16 h1 store
  int tx = tid & 15, ty = tid >> 4;
  float ps[4] = {0.f, 0.f, 0.f, 0.f}, pq2[4] = {0.f, 0.f, 0.f, 0.f};
#pragma unroll
  for (int r = 0; r < 8; r++) {
    int row = ty * 8 + r;
    int sn = __ldg(&send[e0 + row]);
    float4 g = __ldg(&((const float4*)g_xw1)[(size_t)sn * 16 + tx]);
    float4 dv = *(float4*)&Dsm[row * 72 + tx * 4];
    float h0 = dv.x + g.x;
    float h1v = dv.y + g.y;
    float h2 = dv.z + g.z;
    float h3 = dv.w + g.w;
    ps[0] += h0; ps[1] += h1v; ps[2] += h2; ps[3] += h3;
    pq2[0] = fmaf(h0, h0, pq2[0]);
    pq2[1] = fmaf(h1v, h1v, pq2[1]);
    pq2[2] = fmaf(h2, h2, pq2[2]);
    pq2[3] = fmaf(h3, h3, pq2[3]);
    uint2 u;
    __half2 lo = __floats2half2_rn(h0, h1v);
    __half2 hi = __floats2half2_rn(h2, h3);
    u.x = *(unsigned*)&lo;
    u.y = *(unsigned*)&hi;
    g_h1[(size_t)(e0 + row) * 16 + tx] = u;
  }
#pragma unroll
  for (int c = 0; c < 4; c++) {
    ps[c] += __shfl_down_sync(0xffffffffu, ps[c], 16);
    pq2[c] += __shfl_down_sync(0xffffffffu, pq2[c], 16);
  }
  if ((tid & 31) < 16) {
#pragma unroll
    for (int c = 0; c < 4; c++) {
      atomicAdd(&sstats[tx * 4 + c], ps[c]);
      atomicAdd(&sstats[64 + tx * 4 + c], pq2[c]);
    }
  }
  __syncthreads();
  if (tid < 128) atomicAdd(&g_estats[tid], sstats[tid]);
}

// ---------------- BN params from moments ----------------
__global__ void k_bn(const float* __restrict__ gamma, const float* __restrict__ beta,
                     float cinv, int which) {
  int j = threadIdx.x;
  const float* st = which ? g_nstats : g_estats;
  float mean = st[j] * cinv;
  float var = fmaxf(st[64 + j] * cinv - mean * mean, 0.f);
  float sc = gamma[j] * rsqrtf(var + EPSV);
  float sh = beta[j] - mean * sc;
  if (which) { g_nscale[j] = sc; g_nshift[j] = sh; }
  else       { g_escale[j] = sc; g_eshift[j] = sh; }
}

// ---------------- BN+ReLU+scatter-add (fp16 read, vector fp32 atomics) -----
__global__ __launch_bounds__(256) void k_scatter(const int* __restrict__ rec) {
  int gid = blockIdx.x * 256 + threadIdx.x;
  int e = gid >> 2, p = gid & 3;
  int r = __ldg(&rec[e]);
  float4* dst = (float4*)(g_Sa + (size_t)r * 64);
#pragma unroll
  for (int k = 0; k < 4; k++) {
    int c4 = p * 4 + k;
    uint2 u = g_h1[(size_t)e * 16 + c4];
    __half2 lo = *(__half2*)&u.x;
    __half2 hi = *(__half2*)&u.y;
    float2 f0 = __half22float2(lo);
    float2 f1 = __half22float2(hi);
    float4 sc = ((const float4*)g_escale)[c4];
    float4 sh = ((const float4*)g_eshift)[c4];
    float4 a;
    a.x = fmaxf(fmaf(f0.x, sc.x, sh.x), 0.f);
    a.y = fmaxf(fmaf(f0.y, sc.y, sh.y), 0.f);
    a.z = fmaxf(fmaf(f1.x, sc.z, sh.z), 0.f);
    a.w = fmaxf(fmaf(f1.y, sc.w, sh.w), 0.f);
    atomicAdd(dst + c4, a);
  }
  if (p == 0) atomicAdd(&g_cnt[r], 1.f);
}

// ---------------- node GEMM: h1n = [x | Sa/cnt] @ wcomb + b1n + gate*bc -----
__global__ __launch_bounds__(256) void k_node1(const float* __restrict__ x,
                                               const float* __restrict__ b1n) {
  __shared__ float As[64 * 136];
  __shared__ float Ws[32 * 64];
  __shared__ float scnt[64];
  __shared__ float sstats[128];
  int n0 = blockIdx.x * 64;
  int tid = threadIdx.x;
  if (tid < 64) {
    int n = n0 + tid;
    scnt[tid] = (n < NN) ? g_cnt[n] : 0.f;
  }
  if (tid >= 128) sstats[tid - 128] = 0.f;
  __syncthreads();
  for (int i = tid; i < 64 * 32; i += 256) {
    int r = i >> 5, q = i & 31;
    float4 v = make_float4(0.f, 0.f, 0.f, 0.f);
    int n = n0 + r;
    if (n < NN) {
      if (q < 16) v = ((const float4*)x)[(size_t)n * 16 + q];
      else {
        v = ((const float4*)g_Sa)[(size_t)n * 16 + (q - 16)];
        float inv = 1.f / fmaxf(scnt[r], 1.f);
        v.x *= inv; v.y *= inv; v.z *= inv; v.w *= inv;
      }
    }
    *(float4*)&As[r * 136 + q * 4] = v;
  }
  int tx = tid & 15, ty = tid >> 4;
  float acc[4][4] = {};
  for (int kc = 0; kc < 4; kc++) {
    __syncthreads();
    for (int i = tid; i < 32 * 16; i += 256) {
      int r = i >> 4, q = i & 15;
      *(float4*)&Ws[r * 64 + q * 4] = ((const float4*)g_wcomb)[(kc * 32 + r) * 16 + q];
    }
    __syncthreads();
#pragma unroll
    for (int kq = 0; kq < 8; kq++) {
      float4 b0 = *(const float4*)&Ws[(kq * 4 + 0) * 64 + tx * 4];
      float4 b1 = *(const float4*)&Ws[(kq * 4 + 1) * 64 + tx * 4];
      float4 b2 = *(const float4*)&Ws[(kq * 4 + 2) * 64 + tx * 4];
      float4 b3 = *(const float4*)&Ws[(kq * 4 + 3) * 64 + tx * 4];
#pragma unroll
      for (int r = 0; r < 4; r++) {
        float4 a = *(const float4*)&As[(ty * 4 + r) * 136 + kc * 32 + kq * 4];
        MMA_ROW(acc[r], a);
      }
    }
  }
  float4 bias = ((const float4*)b1n)[tx];
  float4 bcv = ((const float4*)g_bc)[tx];
  float ps[4] = {0.f, 0.f, 0.f, 0.f}, pq2[4] = {0.f, 0.f, 0.f, 0.f};
#pragma unroll
  for (int r = 0; r < 4; r++) {
    int row = ty * 4 + r, n = n0 + row;
    if (n < NN) {
      float gate = (scnt[row] > 0.f) ? 1.f : 0.f;
      float h0 = acc[r][0] + bias.x + gate * bcv.x;
      float h1v = acc[r][1] + bias.y + gate * bcv.y;
      float h2 = acc[r][2] + bias.z + gate * bcv.z;
      float h3 = acc[r][3] + bias.w + gate * bcv.w;
      ps[0] += h0; ps[1] += h1v; ps[2] += h2; ps[3] += h3;
      pq2[0] = fmaf(h0, h0, pq2[0]);
      pq2[1] = fmaf(h1v, h1v, pq2[1]);
      pq2[2] = fmaf(h2, h2, pq2[2]);
      pq2[3] = fmaf(h3, h3, pq2[3]);
      ((float4*)g_h1n)[(size_t)n * 16 + tx] = make_float4(h0, h1v, h2, h3);
    }
  }
#pragma unroll
  for (int c = 0; c < 4; c++) {
    ps[c] += __shfl_down_sync(0xffffffffu, ps[c], 16);
    pq2[c] += __shfl_down_sync(0xffffffffu, pq2[c], 16);
  }
  if ((tid & 31) < 16) {
#pragma unroll
    for (int c = 0; c < 4; c++) {
      atomicAdd(&sstats[tx * 4 + c], ps[c]);
      atomicAdd(&sstats[64 + tx * 4 + c], pq2[c]);
    }
  }
  __syncthreads();
  if (tid < 128) atomicAdd(&g_nstats[tid], sstats[tid]);
}

// ---------------- out = relu(bn(h1n)) @ w2n + b2n ----------------
__global__ __launch_bounds__(256) void k_out(const float* __restrict__ w2n,
                                             const float* __restrict__ b2n,
                                             float* __restrict__ out) {
  __shared__ float As[64 * 64];
  __shared__ float Ws[64 * 64];
  __shared__ float ssc[64], ssh[64];
  int n0 = blockIdx.x * 64;
  int tid = threadIdx.x;
  if (tid < 64) { ssc[tid] = g_nscale[tid]; ssh[tid] = g_nshift[tid]; }
  for (int i = tid; i < 64 * 16; i += 256) {
    int r = i >> 4, q = i & 15;
    *(float4*)&Ws[r * 64 + q * 4] = ((const float4*)w2n)[r * 16 + q];
  }
  __syncthreads();
  for (int i = tid; i < 64 * 16; i += 256) {
    int r = i >> 4, q = i & 15;
    float4 v = make_float4(0.f, 0.f, 0.f, 0.f);
    int n = n0 + r;
    if (n < NN) {
      v = ((const float4*)g_h1n)[(size_t)n * 16 + q];
      v.x = fmaxf(fmaf(v.x, ssc[q * 4 + 0], ssh[q * 4 + 0]), 0.f);
      v.y = fmaxf(fmaf(v.y, ssc[q * 4 + 1], ssh[q * 4 + 1]), 0.f);
      v.z = fmaxf(fmaf(v.z, ssc[q * 4 + 2], ssh[q * 4 + 2]), 0.f);
      v.w = fmaxf(fmaf(v.w, ssc[q * 4 + 3], ssh[q * 4 + 3]), 0.f);
    }
    *(float4*)&As[r * 64 + q * 4] = v;
  }
  __syncthreads();
  int tx = tid & 15, ty = tid >> 4;
  float acc[4][4] = {};
#pragma unroll 4
  for (int kq = 0; kq < 16; kq++) {
    float4 b0 = *(const float4*)&Ws[(kq * 4 + 0) * 64 + tx * 4];
    float4 b1 = *(const float4*)&Ws[(kq * 4 + 1) * 64 + tx * 4];
    float4 b2 = *(const float4*)&Ws[(kq * 4 + 2) * 64 + tx * 4];
    float4 b3 = *(const float4*)&Ws[(kq * 4 + 3) * 64 + tx * 4];
#pragma unroll
    for (int r = 0; r < 4; r++) {
      float4 a = *(const float4*)&As[(ty * 4 + r) * 64 + kq * 4];
      MMA_ROW(acc[r], a);
    }
  }
  float4 bias = ((const float4*)b2n)[tx];
#pragma unroll
  for (int r = 0; r < 4; r++) {
    int n = n0 + ty * 4 + r;
    if (n < NN) {
      ((float4*)out)[(size_t)n * 16 + tx] =
          make_float4(acc[r][0] + bias.x, acc[r][1] + bias.y,
                      acc[r][2] + bias.z, acc[r][3] + bias.w);
    }
  }
}

extern "C" void kernel_launch(void* const* d_in, const int* in_sizes, int n_in,
                              void* d_out, int out_size) {
  const float* x   = (const float*)d_in[0];
  const int*   ei  = (const int*)d_in[1];   // [2,E]: send = ei, rec = ei+E
  const float* ea  = (const float*)d_in[2];
  const float* w1m = (const float*)d_in[5];
  const float* b1m = (const float*)d_in[6];
  const float* gm  = (const float*)d_in[7];
  const float* bm  = (const float*)d_in[8];
  const float* w2m = (const float*)d_in[9];
  const float* b2m = (const float*)d_in[10];
  const float* w1n = (const float*)d_in[11];
  const float* b1n = (const float*)d_in[12];
  const float* gn  = (const float*)d_in[13];
  const float* bnb = (const float*)d_in[14];
  const float* w2n = (const float*)d_in[15];
  const float* b2n = (const float*)d_in[16];
  float* out = (float*)d_out;

  const int zero_total = NN * 64 + NN + 256;
  k_zero<<<(zero_total + 255) / 256, 256>>>();
  k_wprep<<<16, 256>>>(w1n, w2m, b2m, w1m);
  k_xw1<<<(NN + 63) / 64, 256>>>(x, w1m, b1m);
  k_edge<<<NE / 128, 256>>>(ea, ei);
  k_bn<<<1, 64>>>(gm, bm, 1.f / (float)NE, 0);
  k_scatter<<<NE * 4 / 256, 256>>>(ei + NE);
  k_node1<<<(NN + 63) / 64, 256>>>(x, b1n);
  k_bn<<<1, 64>>>(gn, bnb, 1.f / (float)NN, 1);
  k_out<<<(NN + 63) / 64, 256>>>(w2n, b2n, out);
}